// round 9
// baseline (speedup 1.0000x reference)
#include <cuda_runtime.h>

#define N_NODES 50000
#define N_EDGES 800000
#define D 64
#define GRID 592                         // 148 SMs x 4 blocks/SM (one wave incl. 152-SM GB300)
#define TPB 256
#define TILE 64
#define NT ((N_NODES + TILE - 1) / TILE) // 782 tiles of 64 rows
#define CH ((N_NODES + GRID - 1) / GRID) // 85 nodes per block chunk
#define HIST_BLKS 448                    // blocks 0..447 histogram; 448..591 self-GEMM overlap

typedef unsigned long long ull;

// ---------------- scratch (static device globals; no allocation) ----------------
__device__ int   g_degcnt[N_NODES];
__device__ int   g_cursor[N_NODES];
__device__ int   g_rs[N_NODES + 1];      // CSR row starts
__device__ int   g_csr[N_EDGES];         // CSR column (src) indices
__device__ int   g_bsum[GRID];
__device__ int   g_boff[GRID];
__device__ int   g_tile[3];              // dyn counters: 0=selfGEMM0, 1=layer0, 2=layer1
__device__ float g_h[N_NODES * D];

// barrier state: monotonic, never reset (safe across graph replays)
__device__ unsigned g_bcnt = 0;
__device__ unsigned g_bgen = 0;

__device__ __forceinline__ void grid_bar() {
    __syncthreads();
    if (threadIdx.x == 0) {
        __threadfence();
        unsigned my = atomicAdd(&g_bcnt, 1u) + 1u;
        unsigned need = (my + GRID - 1u) / GRID;
        if ((my % GRID) == 0u) atomicAdd(&g_bgen, 1u);
        while (*((volatile unsigned*)&g_bgen) < need) {}
        __threadfence();
    }
    __syncthreads();
}

__device__ __forceinline__ int load_idx(const void* p, int e, bool is64) {
    return is64 ? (int)((const long long*)p)[e] : ((const int*)p)[e];
}

// ---------------- f32x2 packed helpers ----------------
__device__ __forceinline__ ull pack2(float a) {
    ull r;
    asm("mov.b64 %0, {%1, %1};" : "=l"(r) : "r"(__float_as_uint(a)));
    return r;
}
__device__ __forceinline__ void ffma2(ull& d, ull a, ull b) {
    asm("fma.rn.f32x2 %0, %1, %2, %0;" : "+l"(d) : "l"(a), "l"(b));
}
__device__ __forceinline__ float lo2(ull v) { return __uint_as_float((unsigned)(v)); }
__device__ __forceinline__ float hi2(ull v) { return __uint_as_float((unsigned)(v >> 32)); }

// ---------------- fused persistent kernel ----------------
__global__ void __launch_bounds__(TPB, 4)
sage_fused_kernel(const float* __restrict__ x,
                  const void* __restrict__ srcp,
                  const void* __restrict__ dstp,
                  const float* __restrict__ W_self0, const float* __restrict__ W_neigh0,
                  const float* __restrict__ b0,
                  const float* __restrict__ W_self1, const float* __restrict__ W_neigh1,
                  const float* __restrict__ b1,
                  float* __restrict__ outp) {
    const int tid = threadIdx.x;
    const int bid = blockIdx.x;
    const int gtid = bid * TPB + tid;
    const int gstride = GRID * TPB;
    const int lane = tid & 31;
    const int w8 = (tid >> 5) * 8;       // GEMM: warp owns rows w8..w8+7
    const int hw = tid >> 4;             // gather: halfwarp 0..15 owns rows hw*4..hw*4+3
    const int l16 = tid & 15;

    __shared__ __align__(16) float Wsm[2][D * D];   // 32 KB
    __shared__ __align__(16) float At[TILE][66];    // 16.9 KB (66 even -> 8B-aligned rows)
    __shared__ int sscan[TPB];                      // 1 KB scan scratch
    __shared__ int rb[TILE + 1];                    // tile row bounds
    __shared__ int s_t;

    // ---- index dtype detection ----
    if (tid == 0) sscan[0] = 0;
    __syncthreads();
    {
        int any = 0;
        const int* si = (const int*)srcp;
        for (int i = tid; i < 2048; i += TPB) any |= si[2 * i + 1];
        if (any) atomicOr(&sscan[0], 1);
    }
    __syncthreads();
    const bool is64 = (sscan[0] == 0);

    // ---- phase A: zero counters ----
    for (int j = gtid; j < N_NODES; j += gstride) { g_degcnt[j] = 0; g_cursor[j] = 0; }
    if (gtid < 3) g_tile[gtid] = 0;
    grid_bar();

    // ---- phase B (role split): histogram || layer-0 self-GEMM -> g_h ----
    if (bid < HIST_BLKS) {
        for (int e = bid * TPB + tid; e < N_EDGES; e += HIST_BLKS * TPB)
            atomicAdd(&g_degcnt[load_idx(dstp, e, is64)], 1);
    } else {
#pragma unroll
        for (int j = 0; j < 4; j++)
            ((float4*)Wsm[0])[tid + j * TPB] = ((const float4*)W_self0)[tid + j * TPB];
        __syncthreads();
        for (;;) {
            if (tid == 0) s_t = atomicAdd(&g_tile[0], 1);
            __syncthreads();
            const int t = s_t;
            if (t >= NT) break;
            const int row0 = t * TILE;
            // stage x tile
#pragma unroll
            for (int j = 0; j < 4; j++) {
                int idx = tid + j * TPB;
                int r = idx >> 4, c = idx & 15;
                int gr = row0 + r;
                float4 v = make_float4(0.f, 0.f, 0.f, 0.f);
                if (gr < N_NODES) v = ((const float4*)(x + (long long)gr * D))[c];
                At[r][c * 4] = v.x; At[r][c * 4 + 1] = v.y;
                At[r][c * 4 + 2] = v.z; At[r][c * 4 + 3] = v.w;
            }
            __syncthreads();
            ull acc[8];
#pragma unroll
            for (int i = 0; i < 8; i++) acc[i] = 0;
#pragma unroll 2
            for (int k = 0; k < D; k += 2) {
                ull w0 = *(const ull*)&Wsm[0][k * D + 2 * lane];
                ull w1 = *(const ull*)&Wsm[0][(k + 1) * D + 2 * lane];
#pragma unroll
                for (int i = 0; i < 8; i++) {
                    float2 a = *(const float2*)&At[w8 + i][k];
                    ffma2(acc[i], pack2(a.x), w0);
                    ffma2(acc[i], pack2(a.y), w1);
                }
            }
#pragma unroll
            for (int i = 0; i < 8; i++) {
                int gr = row0 + w8 + i;
                if (gr < N_NODES) {
                    float2 o; o.x = lo2(acc[i]); o.y = hi2(acc[i]);
                    *(float2*)(g_h + (long long)gr * D + 2 * lane) = o;
                }
            }
            __syncthreads();
        }
    }
    grid_bar();

    // ---- phase C: per-block chunk sums ----
    {
        int n0 = bid * CH;
        int n = N_NODES - n0; if (n > CH) n = CH; if (n < 0) n = 0;
        int v = (tid < n) ? g_degcnt[n0 + tid] : 0;
        sscan[tid] = v; __syncthreads();
        for (int off = TPB / 2; off > 0; off >>= 1) {
            if (tid < off) sscan[tid] += sscan[tid + off];
            __syncthreads();
        }
        if (tid == 0) g_bsum[bid] = sscan[0];
    }
    grid_bar();

    // ---- phase D: block 0 scans the 592 chunk sums ----
    if (bid == 0) {
        int v[3]; int mysum = 0;
#pragma unroll
        for (int k = 0; k < 3; k++) {
            int idx = tid * 3 + k;
            v[k] = (idx < GRID) ? g_bsum[idx] : 0;
            mysum += v[k];
        }
        sscan[tid] = mysum; __syncthreads();
        for (int off = 1; off < TPB; off <<= 1) {
            int t2 = (tid >= off) ? sscan[tid - off] : 0;
            __syncthreads();
            sscan[tid] += t2;
            __syncthreads();
        }
        int run = sscan[tid] - mysum;
#pragma unroll
        for (int k = 0; k < 3; k++) {
            int idx = tid * 3 + k;
            if (idx < GRID) g_boff[idx] = run;
            run += v[k];
        }
    }
    grid_bar();

    // ---- phase E: per-chunk exclusive scan -> row starts ----
    {
        int n0 = bid * CH;
        int n = N_NODES - n0; if (n > CH) n = CH; if (n < 0) n = 0;
        int v = (tid < n) ? g_degcnt[n0 + tid] : 0;
        sscan[tid] = v; __syncthreads();
        for (int off = 1; off < TPB; off <<= 1) {
            int t2 = (tid >= off) ? sscan[tid - off] : 0;
            __syncthreads();
            sscan[tid] += t2;
            __syncthreads();
        }
        if (tid < n) g_rs[n0 + tid] = g_boff[bid] + sscan[tid] - v;
        if (bid == 0 && tid == 0) g_rs[N_NODES] = N_EDGES;
    }
    grid_bar();

    // ---- phase F: fill CSR ----
    for (int e = gtid; e < N_EDGES; e += gstride) {
        int dn = load_idx(dstp, e, is64);
        int s  = load_idx(srcp, e, is64);
        int pos = atomicAdd(&g_cursor[dn], 1);
        g_csr[g_rs[dn] + pos] = s;
    }
    grid_bar();

    // ---- shared tile sub-ops ----
#define STAGE_RB(ROW0)                                                                    \
    if (tid < TILE + 1) {                                                                 \
        int rr = (ROW0) + tid; if (rr > N_NODES) rr = N_NODES;                            \
        rb[tid] = g_rs[rr];                                                               \
    }

#define GATHER_TILE(INP, ROW0)                                                            \
    _Pragma("unroll") for (int i = 0; i < 4; i++) {                                       \
        int r = hw * 4 + i;                                                               \
        int gr = (ROW0) + r;                                                              \
        float4 a0 = make_float4(0,0,0,0), a1 = a0, a2 = a0, a3 = a0;                      \
        float iv = 0.f;                                                                   \
        if (gr < N_NODES) {                                                               \
            int e = rb[r], lend = rb[r + 1];                                              \
            iv = 1.0f / fmaxf((float)(lend - e), 1.0f);                                   \
            for (; e + 3 < lend; e += 4) {                                                \
                int s0 = g_csr[e],     s1 = g_csr[e + 1];                                 \
                int s2 = g_csr[e + 2], s3 = g_csr[e + 3];                                 \
                float4 v0 = __ldg((const float4*)((INP) + (long long)s0 * D) + l16);      \
                float4 v1 = __ldg((const float4*)((INP) + (long long)s1 * D) + l16);      \
                float4 v2 = __ldg((const float4*)((INP) + (long long)s2 * D) + l16);      \
                float4 v3 = __ldg((const float4*)((INP) + (long long)s3 * D) + l16);      \
                a0.x+=v0.x; a0.y+=v0.y; a0.z+=v0.z; a0.w+=v0.w;                           \
                a1.x+=v1.x; a1.y+=v1.y; a1.z+=v1.z; a1.w+=v1.w;                           \
                a2.x+=v2.x; a2.y+=v2.y; a2.z+=v2.z; a2.w+=v2.w;                           \
                a3.x+=v3.x; a3.y+=v3.y; a3.z+=v3.z; a3.w+=v3.w;                           \
            }                                                                             \
            for (; e < lend; e++) {                                                       \
                int s0 = g_csr[e];                                                        \
                float4 v0 = __ldg((const float4*)((INP) + (long long)s0 * D) + l16);      \
                a0.x+=v0.x; a0.y+=v0.y; a0.z+=v0.z; a0.w+=v0.w;                           \
            }                                                                             \
        }                                                                                 \
        At[r][l16*4]   = ((a0.x+a1.x)+(a2.x+a3.x)) * iv;                                  \
        At[r][l16*4+1] = ((a0.y+a1.y)+(a2.y+a3.y)) * iv;                                  \
        At[r][l16*4+2] = ((a0.z+a1.z)+(a2.z+a3.z)) * iv;                                  \
        At[r][l16*4+3] = ((a0.w+a1.w)+(a2.w+a3.w)) * iv;                                  \
    }

#define GEMM_PASS8(WPTR)                                                                  \
    _Pragma("unroll 2") for (int k = 0; k < D; k += 2) {                                  \
        ull w0 = *(const ull*)&(WPTR)[k * D + 2 * lane];                                  \
        ull w1 = *(const ull*)&(WPTR)[(k + 1) * D + 2 * lane];                            \
        _Pragma("unroll") for (int i = 0; i < 8; i++) {                                   \
            float2 a = *(const float2*)&At[w8 + i][k];                                    \
            ffma2(acc[i], pack2(a.x), w0);                                                \
            ffma2(acc[i], pack2(a.y), w1);                                                \
        }                                                                                 \
    }

    // ---- phase G: layer 0 main: g_h = relu(g_h(self) + gather@Wn0 + b0) ----
    {
#pragma unroll
        for (int j = 0; j < 4; j++)
            ((float4*)Wsm[1])[tid + j * TPB] = ((const float4*)W_neigh0)[tid + j * TPB];
        float2 bv = *(const float2*)(b0 + 2 * lane);
        for (;;) {
            __syncthreads();
            if (tid == 0) s_t = atomicAdd(&g_tile[1], 1);
            __syncthreads();
            const int t = s_t;
            if (t >= NT) break;
            const int row0 = t * TILE;
            STAGE_RB(row0)
            __syncthreads();
            GATHER_TILE(x, row0)
            __syncthreads();
            ull acc[8];
#pragma unroll
            for (int i = 0; i < 8; i++) acc[i] = 0;
            GEMM_PASS8(Wsm[1])
#pragma unroll
            for (int i = 0; i < 8; i++) {
                int gr = row0 + w8 + i;
                if (gr < N_NODES) {
                    float2 h2 = *(const float2*)(g_h + (long long)gr * D + 2 * lane);
                    float2 o;
                    o.x = fmaxf(lo2(acc[i]) + h2.x + bv.x, 0.f);
                    o.y = fmaxf(hi2(acc[i]) + h2.y + bv.y, 0.f);
                    *(float2*)(g_h + (long long)gr * D + 2 * lane) = o;
                }
            }
        }
    }
    grid_bar();

    // ---- phase H: layer 1: out = g_h@Ws1 + gather(g_h)@Wn1 + b1 ----
    {
#pragma unroll
        for (int j = 0; j < 4; j++) {
            ((float4*)Wsm[0])[tid + j * TPB] = ((const float4*)W_self1)[tid + j * TPB];
            ((float4*)Wsm[1])[tid + j * TPB] = ((const float4*)W_neigh1)[tid + j * TPB];
        }
        float2 bv = *(const float2*)(b1 + 2 * lane);
        for (;;) {
            __syncthreads();
            if (tid == 0) s_t = atomicAdd(&g_tile[2], 1);
            __syncthreads();
            const int t = s_t;
            if (t >= NT) break;
            const int row0 = t * TILE;
            STAGE_RB(row0)
            // stage self features
#pragma unroll
            for (int j = 0; j < 4; j++) {
                int idx = tid + j * TPB;
                int r = idx >> 4, c = idx & 15;
                int gr = row0 + r;
                float4 v = make_float4(0.f, 0.f, 0.f, 0.f);
                if (gr < N_NODES) v = ((const float4*)(g_h + (long long)gr * D))[c];
                At[r][c * 4] = v.x; At[r][c * 4 + 1] = v.y;
                At[r][c * 4 + 2] = v.z; At[r][c * 4 + 3] = v.w;
            }
            __syncthreads();
            ull acc[8];
#pragma unroll
            for (int i = 0; i < 8; i++) acc[i] = 0;
            GEMM_PASS8(Wsm[0])
            __syncthreads();
            GATHER_TILE(g_h, row0)
            __syncthreads();
            GEMM_PASS8(Wsm[1])
#pragma unroll
            for (int i = 0; i < 8; i++) {
                int gr = row0 + w8 + i;
                if (gr < N_NODES) {
                    float2 o;
                    o.x = lo2(acc[i]) + bv.x;
                    o.y = hi2(acc[i]) + bv.y;
                    *(float2*)(outp + (long long)gr * D + 2 * lane) = o;
                }
            }
        }
    }
}

// ---------------- launch: ONE kernel = ONE graph node ----------------
extern "C" void kernel_launch(void* const* d_in, const int* in_sizes, int n_in,
                              void* d_out, int out_size) {
    const float* x        = (const float*)d_in[0];
    const void*  src      = d_in[1];
    const void*  dst      = d_in[2];
    const float* W_self0  = (const float*)d_in[3];
    const float* W_neigh0 = (const float*)d_in[4];
    const float* b0       = (const float*)d_in[5];
    const float* W_self1  = (const float*)d_in[6];
    const float* W_neigh1 = (const float*)d_in[7];
    const float* b1       = (const float*)d_in[8];
    float* outp = (float*)d_out;

    sage_fused_kernel<<<GRID, TPB>>>(x, src, dst,
                                     W_self0, W_neigh0, b0,
                                     W_self1, W_neigh1, b1, outp);
}